// round 3
// baseline (speedup 1.0000x reference)
#include <cuda_runtime.h>
#include <cuda_fp16.h>
#include <cstdint>

// Shapes: x[4,1024,4096] f32, qweight[512,11008] i32 (8x4b along K),
// qzeros[32,1376] i32 (8x4b along N), scales[32,11008] f32, out[4096,11008] f32.
#define MDIM 4096
#define KDIM 4096
#define NDIM 11008
#define GQ   128           // quant group along K

#define BM 128
#define BN 256
#define BK 32
#define STAGES 4
#define THREADS 256
#define NIT (KDIM / BK)          // 128
#define GRID_M (MDIM / BM)       // 32
#define GRID_N (NDIM / BN)       // 43

// padded smem rows: 32 halfs + 8 pad = 40 halfs = 80B
#define LDS_ROW 80
#define A_STAGE_BYTES (BM * LDS_ROW)            // 10240
#define B_STAGE_BYTES (BN * LDS_ROW)            // 20480
#define STAGE_BYTES (A_STAGE_BYTES + B_STAGE_BYTES)  // 30720
#define SMEM_TOTAL (STAGE_BYTES * STAGES)       // 122880

// fp16 staging of A (x) and dequantized W^T (N-major, K contiguous)
__device__ __align__(16) __half g_xh[(size_t)MDIM * KDIM];   // 33.5 MB
__device__ __align__(16) __half g_wt[(size_t)NDIM * KDIM];   // 90.2 MB

// ---------------- prepass 1: x fp32 -> fp16 row-major ----------------
__global__ void cvt_x_kernel(const float* __restrict__ x) {
    size_t idx = (size_t)blockIdx.x * blockDim.x + threadIdx.x;   // one uint4 (8 halfs)
    if (idx >= (size_t)MDIM * KDIM / 8) return;
    const float4* xp = reinterpret_cast<const float4*>(x) + idx * 2;
    float4 a = xp[0], b = xp[1];
    __half2 h0 = __floats2half2_rn(a.x, a.y);
    __half2 h1 = __floats2half2_rn(a.z, a.w);
    __half2 h2 = __floats2half2_rn(b.x, b.y);
    __half2 h3 = __floats2half2_rn(b.z, b.w);
    uint4 o;
    o.x = *reinterpret_cast<uint32_t*>(&h0);
    o.y = *reinterpret_cast<uint32_t*>(&h1);
    o.z = *reinterpret_cast<uint32_t*>(&h2);
    o.w = *reinterpret_cast<uint32_t*>(&h3);
    reinterpret_cast<uint4*>(g_xh)[idx] = o;
}

// ---------------- prepass 2: dequant 4-bit -> fp16, transpose to [N][K] ----------------
__global__ void dequant_kernel(const int* __restrict__ qweight,
                               const int* __restrict__ qzeros,
                               const float* __restrict__ scales) {
    size_t idx = (size_t)blockIdx.x * blockDim.x + threadIdx.x;   // (kp, n) pair
    if (idx >= (size_t)(KDIM / 8) * NDIM) return;
    int kp = (int)(idx / NDIM);
    int n  = (int)(idx % NDIM);
    int g  = kp >> 4;   // (kp*8)/128
    uint32_t q = (uint32_t)qweight[idx];
    int z = ((uint32_t)qzeros[g * (NDIM / 8) + (n >> 3)] >> ((n & 7) * 4)) & 0xF;
    float s = scales[(size_t)g * NDIM + n];
    __half h[8];
    #pragma unroll
    for (int i = 0; i < 8; ++i) {
        int v = (q >> (4 * i)) & 0xF;
        h[i] = __float2half_rn((float)(v - z) * s);
    }
    *reinterpret_cast<uint4*>(&g_wt[(size_t)n * KDIM + (size_t)kp * 8]) =
        *reinterpret_cast<uint4*>(h);
}

// ---------------- PTX helpers ----------------
__device__ __forceinline__ void ldsm4(uint32_t* r, uint32_t addr) {
    asm volatile("ldmatrix.sync.aligned.m8n8.x4.shared.b16 {%0,%1,%2,%3}, [%4];"
                 : "=r"(r[0]), "=r"(r[1]), "=r"(r[2]), "=r"(r[3]) : "r"(addr));
}
__device__ __forceinline__ void mma16816(float* c, const uint32_t* a, uint32_t b0, uint32_t b1) {
    asm volatile("mma.sync.aligned.m16n8k16.row.col.f32.f16.f16.f32 "
                 "{%0,%1,%2,%3}, {%4,%5,%6,%7}, {%8,%9}, {%0,%1,%2,%3};"
                 : "+f"(c[0]), "+f"(c[1]), "+f"(c[2]), "+f"(c[3])
                 : "r"(a[0]), "r"(a[1]), "r"(a[2]), "r"(a[3]), "r"(b0), "r"(b1));
}
__device__ __forceinline__ void cp_async16(uint32_t dst, const void* src) {
    asm volatile("cp.async.cg.shared.global [%0], [%1], 16;" :: "r"(dst), "l"(src));
}
#define CP_COMMIT() asm volatile("cp.async.commit_group;" ::: "memory")
#define CP_WAIT(N)  asm volatile("cp.async.wait_group %0;" :: "n"(N) : "memory")

// ---------------- main GEMM ----------------
__global__ void __launch_bounds__(THREADS) gemm_kernel(float* __restrict__ out) {
    extern __shared__ __align__(16) char smem[];
    const uint32_t smem_base = (uint32_t)__cvta_generic_to_shared(smem);

    const int t = threadIdx.x;
    const int wid = t >> 5;
    const int lane = t & 31;

    const int mtile = blockIdx.x & 31;          // mtile fastest: concurrent CTAs share B slices + all of A in L2
    const int ntile = blockIdx.x >> 5;
    const int m0 = mtile * BM;
    const int n0 = ntile * BN;

    const int warp_m = wid >> 2;                // 0..1 -> 64-row slab
    const int warp_n = wid & 3;                 // 0..3 -> 64-col slab

    float acc[4][8][4];
    #pragma unroll
    for (int i = 0; i < 4; ++i)
        #pragma unroll
        for (int j = 0; j < 8; ++j)
            #pragma unroll
            for (int k = 0; k < 4; ++k) acc[i][j][k] = 0.f;

    // ---- cp.async load of one stage ----
    const __half* gA = g_xh + (size_t)m0 * KDIM;
    const __half* gB = g_wt + (size_t)n0 * KDIM;

    auto load_stage = [&](int s, int kblk) {
        const int k0 = kblk * BK;
        uint32_t base = smem_base + s * STAGE_BYTES;
        #pragma unroll
        for (int j = 0; j < 2; ++j) {           // A: 512 x 16B chunks
            int idx = j * 256 + t;
            int row = idx >> 2, c = idx & 3;
            cp_async16(base + row * LDS_ROW + c * 16,
                       gA + (size_t)row * KDIM + k0 + c * 8);
        }
        #pragma unroll
        for (int j = 0; j < 4; ++j) {           // B: 1024 x 16B chunks
            int idx = j * 256 + t;
            int row = idx >> 2, c = idx & 3;
            cp_async16(base + A_STAGE_BYTES + row * LDS_ROW + c * 16,
                       gB + (size_t)row * KDIM + k0 + c * 8);
        }
        CP_COMMIT();
    };

    // prologue
    #pragma unroll
    for (int s = 0; s < STAGES - 1; ++s) load_stage(s, s);

    // ldmatrix address components (per-thread, stage-invariant parts)
    const int a_row = warp_m * 64 + (lane & 15);
    const int a_col8 = (lane >> 4) * 8;                       // halfs
    const int b_row = warp_n * 64 + ((lane >> 3) & 1) * 8 + (lane & 7);
    const int b_col8 = (lane >> 4) * 8;

    #pragma unroll 1
    for (int it = 0; it < NIT; ++it) {
        CP_WAIT(STAGES - 2);
        __syncthreads();

        if (it + STAGES - 1 < NIT) load_stage((it + STAGES - 1) % STAGES, it + STAGES - 1);

        const int s = it % STAGES;
        const uint32_t aBase = smem_base + s * STAGE_BYTES;
        const uint32_t bBase = aBase + A_STAGE_BYTES;

        #pragma unroll
        for (int kh = 0; kh < 2; ++kh) {        // two k16 halves of BK=32
            uint32_t afrag[4][4];
            #pragma unroll
            for (int mi = 0; mi < 4; ++mi)
                ldsm4(afrag[mi], aBase + (a_row + mi * 16) * LDS_ROW + (kh * 16 + a_col8) * 2);
            #pragma unroll
            for (int np = 0; np < 4; ++np) {    // each covers two n8 subtiles
                uint32_t bfrag[4];
                ldsm4(bfrag, bBase + (b_row + np * 16) * LDS_ROW + (kh * 16 + b_col8) * 2);
                #pragma unroll
                for (int mi = 0; mi < 4; ++mi) {
                    mma16816(acc[mi][2 * np],     afrag[mi], bfrag[0], bfrag[2]);
                    mma16816(acc[mi][2 * np + 1], afrag[mi], bfrag[1], bfrag[3]);
                }
            }
        }
    }
    CP_WAIT(0);

    // ---- epilogue: direct stores (float2 per c-frag half) ----
    const int mBase = m0 + warp_m * 64;
    const int nBase = n0 + warp_n * 64;
    const int r0 = lane >> 2;          // 0..7
    const int cpair = (lane & 3) * 2;  // 0,2,4,6
    #pragma unroll
    for (int mi = 0; mi < 4; ++mi) {
        #pragma unroll
        for (int ni = 0; ni < 8; ++ni) {
            float* p0 = out + (size_t)(mBase + mi * 16 + r0) * NDIM + nBase + ni * 8 + cpair;
            float* p1 = out + (size_t)(mBase + mi * 16 + r0 + 8) * NDIM + nBase + ni * 8 + cpair;
            *reinterpret_cast<float2*>(p0) = make_float2(acc[mi][ni][0], acc[mi][ni][1]);
            *reinterpret_cast<float2*>(p1) = make_float2(acc[mi][ni][2], acc[mi][ni][3]);
        }
    }
}

extern "C" void kernel_launch(void* const* d_in, const int* in_sizes, int n_in,
                              void* d_out, int out_size) {
    const float* x  = (const float*)d_in[0];
    const int* qw   = (const int*)d_in[1];
    const int* qz   = (const int*)d_in[2];
    const float* sc = (const float*)d_in[3];
    float* out      = (float*)d_out;

    cudaFuncSetAttribute(gemm_kernel, cudaFuncAttributeMaxDynamicSharedMemorySize, SMEM_TOTAL);

    cvt_x_kernel<<<(MDIM * KDIM / 8 + 255) / 256, 256>>>(x);
    dequant_kernel<<<((KDIM / 8) * NDIM + 255) / 256, 256>>>(qw, qz, sc);
    gemm_kernel<<<GRID_M * GRID_N, THREADS, SMEM_TOTAL>>>(out);
}

// round 4
// speedup vs baseline: 1.3931x; 1.3931x over previous
#include <cuda_runtime.h>
#include <cuda_fp16.h>
#include <cstdint>

// Shapes: x[4,1024,4096] f32, qweight[512,11008] i32 (8x4b along K),
// qzeros[32,1376] i32 (8x4b along N), scales[32,11008] f32, out[4096,11008] f32.
#define MDIM 4096
#define KDIM 4096
#define NDIM 11008

#define BM 128
#define BN 256
#define BK 64
#define STAGES 3
#define THREADS 256
#define NIT (KDIM / BK)          // 64
#define GRID_M (MDIM / BM)       // 32
#define GRID_N (NDIM / BN)       // 43

// 128B rows with XOR swizzle (conflict-free cp.async writes + ldmatrix reads)
#define ROWB 128
#define A_STAGE_BYTES (BM * ROWB)                    // 16384
#define B_STAGE_BYTES (BN * ROWB)                    // 32768
#define STAGE_BYTES (A_STAGE_BYTES + B_STAGE_BYTES)  // 49152
#define SMEM_TOTAL (STAGE_BYTES * STAGES)            // 147456

// fp16 staging of A (x) and dequantized W^T (N-major, K contiguous)
__device__ __align__(16) __half g_xh[(size_t)MDIM * KDIM];   // 33.5 MB
__device__ __align__(16) __half g_wt[(size_t)NDIM * KDIM];   // 90.2 MB

// ---------------- prepass 1: x fp32 -> fp16 row-major ----------------
__global__ void cvt_x_kernel(const float* __restrict__ x) {
    size_t idx = (size_t)blockIdx.x * blockDim.x + threadIdx.x;   // one uint4 (8 halfs)
    if (idx >= (size_t)MDIM * KDIM / 8) return;
    const float4* xp = reinterpret_cast<const float4*>(x) + idx * 2;
    float4 a = xp[0], b = xp[1];
    __half2 h0 = __floats2half2_rn(a.x, a.y);
    __half2 h1 = __floats2half2_rn(a.z, a.w);
    __half2 h2 = __floats2half2_rn(b.x, b.y);
    __half2 h3 = __floats2half2_rn(b.z, b.w);
    uint4 o;
    o.x = *reinterpret_cast<uint32_t*>(&h0);
    o.y = *reinterpret_cast<uint32_t*>(&h1);
    o.z = *reinterpret_cast<uint32_t*>(&h2);
    o.w = *reinterpret_cast<uint32_t*>(&h3);
    reinterpret_cast<uint4*>(g_xh)[idx] = o;
}

// ---------------- prepass 2: dequant + transpose via smem tile ----------------
// block: 64 n x 64 k tile. Phase 1: coalesced qweight reads -> dequant -> smem.
// Phase 2: coalesced 128B warp-wide writes of g_wt rows (N-major, K contiguous).
__global__ void __launch_bounds__(256) dequant_kernel(const int* __restrict__ qweight,
                                                      const int* __restrict__ qzeros,
                                                      const float* __restrict__ scales) {
    __shared__ __align__(16) uint8_t tile[64 * 128];
    const int t = threadIdx.x;
    const int n0 = blockIdx.x * 64;
    const int k0 = blockIdx.y * 64;          // in halfs
    const int kp0 = blockIdx.y * 8;          // packed-int32 row base
    const int g = k0 >> 7;                   // quant group (GROUP=128)

    const int nl = t & 63;
    const int n = n0 + nl;
    const int z = ((uint32_t)qzeros[g * (NDIM / 8) + (n >> 3)] >> ((n & 7) * 4)) & 0xF;
    const float s = scales[(size_t)g * NDIM + n];

    #pragma unroll
    for (int i = 0; i < 2; ++i) {
        int item = i * 256 + t;
        int kp = item >> 6;                  // 0..7
        uint32_t q = (uint32_t)qweight[(size_t)(kp0 + kp) * NDIM + n];
        __half h[8];
        #pragma unroll
        for (int j = 0; j < 8; ++j) {
            int v = (q >> (4 * j)) & 0xF;
            h[j] = __float2half_rn((float)(v - z) * s);
        }
        int colb = (kp * 16) ^ ((nl & 7) << 4);
        *reinterpret_cast<uint4*>(tile + nl * 128 + colb) = *reinterpret_cast<uint4*>(h);
    }
    __syncthreads();
    #pragma unroll
    for (int i = 0; i < 8; ++i) {
        int idx = i * 256 + t;
        int row = idx >> 5, col = idx & 31;  // col in uint32 units
        uint32_t v = *reinterpret_cast<uint32_t*>(tile + row * 128 + ((col * 4) ^ ((row & 7) << 4)));
        *reinterpret_cast<uint32_t*>(&g_wt[(size_t)(n0 + row) * KDIM + k0 + col * 2]) = v;
    }
}

// ---------------- PTX helpers ----------------
__device__ __forceinline__ void ldsm4(uint32_t* r, uint32_t addr) {
    asm volatile("ldmatrix.sync.aligned.m8n8.x4.shared.b16 {%0,%1,%2,%3}, [%4];"
                 : "=r"(r[0]), "=r"(r[1]), "=r"(r[2]), "=r"(r[3]) : "r"(addr));
}
__device__ __forceinline__ void mma16816(float* c, const uint32_t* a, uint32_t b0, uint32_t b1) {
    asm volatile("mma.sync.aligned.m16n8k16.row.col.f32.f16.f16.f32 "
                 "{%0,%1,%2,%3}, {%4,%5,%6,%7}, {%8,%9}, {%0,%1,%2,%3};"
                 : "+f"(c[0]), "+f"(c[1]), "+f"(c[2]), "+f"(c[3])
                 : "r"(a[0]), "r"(a[1]), "r"(a[2]), "r"(a[3]), "r"(b0), "r"(b1));
}
__device__ __forceinline__ void cp_async16(uint32_t dst, const void* src) {
    asm volatile("cp.async.cg.shared.global [%0], [%1], 16;" :: "r"(dst), "l"(src));
}
#define CP_COMMIT() asm volatile("cp.async.commit_group;" ::: "memory")
#define CP_WAIT(N)  asm volatile("cp.async.wait_group %0;" :: "n"(N) : "memory")

// ---------------- main GEMM ----------------
__global__ void __launch_bounds__(THREADS, 1) gemm_kernel(float* __restrict__ out) {
    extern __shared__ __align__(16) char smem[];
    const uint32_t smem_base = (uint32_t)__cvta_generic_to_shared(smem);

    const int t = threadIdx.x;
    const int wid = t >> 5;
    const int lane = t & 31;

    const int mtile = blockIdx.x & 31;          // mtile fastest: wave shares B slices + A in L2
    const int ntile = blockIdx.x >> 5;
    const int m0 = mtile * BM;
    const int n0 = ntile * BN;

    const int warp_m = wid >> 2;                // 0..1 -> 64-row slab
    const int warp_n = wid & 3;                 // 0..3 -> 64-col slab

    float acc[4][8][4];
    #pragma unroll
    for (int i = 0; i < 4; ++i)
        #pragma unroll
        for (int j = 0; j < 8; ++j)
            #pragma unroll
            for (int k = 0; k < 4; ++k) acc[i][j][k] = 0.f;

    const __half* gA = g_xh + (size_t)m0 * KDIM;
    const __half* gB = g_wt + (size_t)n0 * KDIM;

    auto load_stage = [&](int s, int kblk) {
        const int k0 = kblk * BK;
        uint32_t base = smem_base + s * STAGE_BYTES;
        #pragma unroll
        for (int j = 0; j < 4; ++j) {           // A: 1024 x 16B chunks
            int idx = j * 256 + t;
            int row = idx >> 3, c = idx & 7;
            cp_async16(base + row * ROWB + ((c * 16) ^ ((row & 7) << 4)),
                       gA + (size_t)row * KDIM + k0 + c * 8);
        }
        #pragma unroll
        for (int j = 0; j < 8; ++j) {           // B: 2048 x 16B chunks
            int idx = j * 256 + t;
            int row = idx >> 3, c = idx & 7;
            cp_async16(base + A_STAGE_BYTES + row * ROWB + ((c * 16) ^ ((row & 7) << 4)),
                       gB + (size_t)row * KDIM + k0 + c * 8);
        }
        CP_COMMIT();
    };

    // prologue: STAGES-1 stages in flight
    #pragma unroll
    for (int s = 0; s < STAGES - 1; ++s) load_stage(s, s);

    // per-thread ldmatrix address components
    const int rA = lane & 15;                       // A row-within-16
    const int cA = (lane >> 4) * 16;                // A col byte (within k16)
    const int swzA = (lane & 7) << 4;
    const int rB = ((lane >> 3) & 1) * 8 + (lane & 7);
    const int cB = (lane >> 4) * 16;
    const int swzB = (lane & 7) << 4;

    uint32_t afrag[2][4][4];
    uint32_t bfrag[2][4][4];

    #pragma unroll 1
    for (int it = 0; it < NIT; ++it) {
        CP_WAIT(STAGES - 2);
        __syncthreads();

        if (it + STAGES - 1 < NIT) load_stage((it + STAGES - 1) % STAGES, it + STAGES - 1);

        const int s = it % STAGES;
        const uint32_t aBase = smem_base + s * STAGE_BYTES;
        const uint32_t bBase = aBase + A_STAGE_BYTES;

        // preload kh=0 fragments
        #pragma unroll
        for (int mi = 0; mi < 4; ++mi) {
            int row = warp_m * 64 + mi * 16 + rA;
            ldsm4(afrag[0][mi], aBase + row * ROWB + ((cA) ^ swzA));
        }
        #pragma unroll
        for (int np = 0; np < 4; ++np) {
            int row = warp_n * 64 + np * 16 + rB;
            ldsm4(bfrag[0][np], bBase + row * ROWB + ((cB) ^ swzB));
        }

        #pragma unroll
        for (int kh = 0; kh < 4; ++kh) {        // four k16 steps of BK=64
            const int cur = kh & 1, nxt = cur ^ 1;
            if (kh < 3) {
                int colb = (kh + 1) * 32;
                #pragma unroll
                for (int mi = 0; mi < 4; ++mi) {
                    int row = warp_m * 64 + mi * 16 + rA;
                    ldsm4(afrag[nxt][mi], aBase + row * ROWB + ((colb + cA) ^ swzA));
                }
                #pragma unroll
                for (int np = 0; np < 4; ++np) {
                    int row = warp_n * 64 + np * 16 + rB;
                    ldsm4(bfrag[nxt][np], bBase + row * ROWB + ((colb + cB) ^ swzB));
                }
            }
            #pragma unroll
            for (int np = 0; np < 4; ++np)
                #pragma unroll
                for (int mi = 0; mi < 4; ++mi) {
                    mma16816(acc[mi][2 * np],     afrag[cur][mi], bfrag[cur][np][0], bfrag[cur][np][2]);
                    mma16816(acc[mi][2 * np + 1], afrag[cur][mi], bfrag[cur][np][1], bfrag[cur][np][3]);
                }
        }
    }
    CP_WAIT(0);

    // ---- epilogue: direct float2 stores ----
    const int mBase = m0 + warp_m * 64;
    const int nBase = n0 + warp_n * 64;
    const int r0 = lane >> 2;
    const int cpair = (lane & 3) * 2;
    #pragma unroll
    for (int mi = 0; mi < 4; ++mi) {
        #pragma unroll
        for (int ni = 0; ni < 8; ++ni) {
            float* p0 = out + (size_t)(mBase + mi * 16 + r0) * NDIM + nBase + ni * 8 + cpair;
            float* p1 = out + (size_t)(mBase + mi * 16 + r0 + 8) * NDIM + nBase + ni * 8 + cpair;
            *reinterpret_cast<float2*>(p0) = make_float2(acc[mi][ni][0], acc[mi][ni][1]);
            *reinterpret_cast<float2*>(p1) = make_float2(acc[mi][ni][2], acc[mi][ni][3]);
        }
    }
}

extern "C" void kernel_launch(void* const* d_in, const int* in_sizes, int n_in,
                              void* d_out, int out_size) {
    const float* x  = (const float*)d_in[0];
    const int* qw   = (const int*)d_in[1];
    const int* qz   = (const int*)d_in[2];
    const float* sc = (const float*)d_in[3];
    float* out      = (float*)d_out;

    cudaFuncSetAttribute(gemm_kernel, cudaFuncAttributeMaxDynamicSharedMemorySize, SMEM_TOTAL);

    cvt_x_kernel<<<(MDIM * KDIM / 8 + 255) / 256, 256>>>(x);
    dim3 dq_grid(NDIM / 64, KDIM / 64);
    dequant_kernel<<<dq_grid, 256>>>(qw, qz, sc);
    gemm_kernel<<<GRID_M * GRID_N, THREADS, SMEM_TOTAL>>>(out);
}